// round 7
// baseline (speedup 1.0000x reference)
#include <cuda_runtime.h>
#include <cuda_bf16.h>
#include <math.h>
#include <stdint.h>

// Problem constants
#define NN    4096
#define DD    64
#define HH    4
#define OO    64
#define KK    2
#define KHT   8        // K*H
#define NUSER 4000
#define CC    2

// Device scratch (allocation-free rule: static __device__ arrays)
__device__ float         g_hp [KHT * NN * OO];   // h_prime[kh][n][o]  fp32 (8 MB)
__device__ __nv_bfloat16 g_hpT[KHT * OO * NN];   // h_prime transposed [kh][o][m] bf16 (4 MB)
__device__ float         g_att[KHT * NN * OO];   // attention output per (k,h)  (8 MB)
__device__ float g_thr [KHT * NN];       // -src[n]
__device__ float g_es1 [KHT * NN];       // exp(src)
__device__ float g_es2 [KHT * NN];       // exp(0.2*src)
__device__ float g_dstv[KHT * NN];       // dst[m]
__device__ float g_ed1 [KHT * NN];       // exp(dst)
__device__ float g_ed2 [KHT * NN];       // exp(0.2*dst)

// ---------------------------------------------------------------------------
// Arch-agnostic tensor-core helpers (generic PTX, works on compute_103)
// ---------------------------------------------------------------------------
__device__ __forceinline__ uint32_t smem_u32(const void* p) {
    uint32_t a;
    asm("{ .reg .u64 t; cvta.to.shared.u64 t, %1; cvt.u32.u64 %0, t; }" : "=r"(a) : "l"(p));
    return a;
}
__device__ __forceinline__ void ldsm_x4(uint32_t* r, uint32_t addr) {
    asm volatile("ldmatrix.sync.aligned.m8n8.x4.shared.b16 {%0,%1,%2,%3}, [%4];"
        : "=r"(r[0]), "=r"(r[1]), "=r"(r[2]), "=r"(r[3]) : "r"(addr));
}
__device__ __forceinline__ void mma16816(float* c, const uint32_t* a, const uint32_t* b) {
    asm volatile("mma.sync.aligned.m16n8k16.row.col.f32.bf16.bf16.f32 "
        "{%0,%1,%2,%3}, {%4,%5,%6,%7}, {%8,%9}, {%0,%1,%2,%3};"
        : "+f"(c[0]), "+f"(c[1]), "+f"(c[2]), "+f"(c[3])
        : "r"(a[0]), "r"(a[1]), "r"(a[2]), "r"(a[3]), "r"(b[0]), "r"(b[1]));
}

// ---------------------------------------------------------------------------
// Kernel 1: h_prime = h @ w, plus bf16 transposed copy for the MMA B operand.
// grid (N/64, KH), 256 threads.
// ---------------------------------------------------------------------------
__global__ void k_hproj(const float* __restrict__ h, const float* __restrict__ w) {
    const int kh = blockIdx.y;
    const int n0 = blockIdx.x * 64;
    __shared__ float shT[64][68];     // [d][i]  (transposed h tile)
    __shared__ float buf[64 * 68];    // first 4096 floats: w tile; reused as [o][n] (stride 68)
    const int tid = threadIdx.x;

    const float4* wkh = (const float4*)(w + (size_t)kh * 64 * 64);
    #pragma unroll
    for (int it = 0; it < 4; it++) ((float4*)buf)[tid + it * 256] = wkh[tid + it * 256];

    {
        const int d = tid & 63, ig0 = tid >> 6;
        #pragma unroll
        for (int it = 0; it < 4; it++) {
            const int ig = ig0 + it * 4;
            float4 v;
            v.x = h[(size_t)(n0 + ig * 4 + 0) * DD + d];
            v.y = h[(size_t)(n0 + ig * 4 + 1) * DD + d];
            v.z = h[(size_t)(n0 + ig * 4 + 2) * DD + d];
            v.w = h[(size_t)(n0 + ig * 4 + 3) * DD + d];
            *(float4*)&shT[d][ig * 4] = v;
        }
    }
    __syncthreads();

    const int ty = tid >> 4, tx = tid & 15;
    float acc[4][4] = {};
    #pragma unroll 8
    for (int j = 0; j < 64; j++) {
        const float4 pv = *(const float4*)&shT[j][ty * 4];
        const float4 hv = *(const float4*)&buf[j * 64 + tx * 4];
        acc[0][0] += pv.x * hv.x; acc[0][1] += pv.x * hv.y; acc[0][2] += pv.x * hv.z; acc[0][3] += pv.x * hv.w;
        acc[1][0] += pv.y * hv.x; acc[1][1] += pv.y * hv.y; acc[1][2] += pv.y * hv.z; acc[1][3] += pv.y * hv.w;
        acc[2][0] += pv.z * hv.x; acc[2][1] += pv.z * hv.y; acc[2][2] += pv.z * hv.z; acc[2][3] += pv.z * hv.w;
        acc[3][0] += pv.w * hv.x; acc[3][1] += pv.w * hv.y; acc[3][2] += pv.w * hv.z; acc[3][3] += pv.w * hv.w;
    }
    // fp32 h_prime (for k_attvec)
    float* hp = g_hp + (size_t)kh * NN * OO;
    #pragma unroll
    for (int r = 0; r < 4; r++) {
        float4 v = make_float4(acc[r][0], acc[r][1], acc[r][2], acc[r][3]);
        *(float4*)&hp[(size_t)(n0 + ty * 4 + r) * OO + tx * 4] = v;
    }
    __syncthreads();            // done reading buf as w-tile
    // transpose into buf as [o][n_local], stride 68 to avoid conflicts
    #pragma unroll
    for (int r = 0; r < 4; r++)
        #pragma unroll
        for (int c = 0; c < 4; c++)
            buf[(tx * 4 + c) * 68 + ty * 4 + r] = acc[r][c];
    __syncthreads();
    // write bf16 transposed rows: thread -> row o = tid>>2, 16 n values
    {
        const int o = tid >> 2, nc = (tid & 3) * 16;
        __nv_bfloat162 tmp[8];
        #pragma unroll
        for (int j = 0; j < 8; j++)
            tmp[j] = __floats2bfloat162_rn(buf[o * 68 + nc + 2 * j], buf[o * 68 + nc + 2 * j + 1]);
        __nv_bfloat16* dst = g_hpT + ((size_t)kh * 64 + o) * NN + n0 + nc;
        *(uint4*)dst       = ((uint4*)tmp)[0];
        *(uint4*)(dst + 8) = ((uint4*)tmp)[1];
    }
}

// ---------------------------------------------------------------------------
// Kernel 2: src/dst attention scalars + factorized exponentials.
// ---------------------------------------------------------------------------
__global__ void k_attvec(const float* __restrict__ a_src, const float* __restrict__ a_dst) {
    const int wg   = blockIdx.x * 8 + (threadIdx.x >> 5);
    const int lane = threadIdx.x & 31;
    const int kh = wg >> 12;
    const int n  = wg & (NN - 1);
    const float* hp = g_hp + ((size_t)kh * NN + n) * OO;
    const float t1 = tanhf(hp[lane]);
    const float t2 = tanhf(hp[lane + 32]);
    float as = t1 * a_src[kh * 64 + lane] + t2 * a_src[kh * 64 + lane + 32];
    float ad = t1 * a_dst[kh * 64 + lane] + t2 * a_dst[kh * 64 + lane + 32];
    #pragma unroll
    for (int off = 16; off; off >>= 1) {
        as += __shfl_xor_sync(0xFFFFFFFFu, as, off);
        ad += __shfl_xor_sync(0xFFFFFFFFu, ad, off);
    }
    if (lane == 0) {
        const int idx = kh * NN + n;
        g_thr [idx] = -as;
        g_es1 [idx] = expf(as);
        g_es2 [idx] = expf(0.2f * as);
        g_dstv[idx] = ad;
        g_ed1 [idx] = expf(ad);
        g_ed2 [idx] = expf(0.2f * ad);
    }
}

// ---------------------------------------------------------------------------
// Kernel 3 (dominant, mma.sync bf16): ONE head per CTA (occupancy 2/SM):
//   D[128,64] += P[128,64]_bf16 @ HpT[64(o),64(m)]_bf16^T   (chunks over m)
//   P[n,m] = adj[k][n][m] * (dst[m] >= -src[n] ? es1[n]*ed1[m] : es2[n]*ed2[m])
// grid (N/128=32, K=2, H=4), 256 threads (8 warps), dynamic smem ~29KB.
//
// smem (bytes from base):
//   P tile : [128 rows x 72 bf16 (144B stride)] = 18432
//   B tile : [ 64 rows x 72 bf16 (144B stride)] =  9216
//   m-vecs : 3 x 64 floats                      =   768
//   den    : 128 floats                         =   512
// ---------------------------------------------------------------------------
#define P_OFF   0
#define B_OFF   18432
#define V_OFF   27648
#define D_OFF   28416
#define SMEM_DYN 28928

__global__ void __launch_bounds__(256, 2) k_main4(const float* __restrict__ adj) {
    extern __shared__ char sm[];
    const uint32_t smb = smem_u32(sm);
    const int tid  = threadIdx.x;
    const int wid  = tid >> 5;
    const int lane = tid & 31;
    const int k    = blockIdx.y;
    const int hh   = blockIdx.z;
    const int n0   = blockIdx.x * 128;
    const int kh   = k * HH + hh;

    // ---- row-side (n) constants: thread pair (2*i, 2*i+1) owns row i ----
    const int i = tid >> 1;
    const int ridx = kh * NN + n0 + i;
    const float thr = g_thr[ridx];
    const float E1  = g_es1[ridx];
    const float E2  = g_es2[ridx];
    const float* adjrow = adj + (size_t)k * NN * NN + (size_t)(n0 + i) * NN;
    const int mhalf = (tid & 1) * 32;

    // m-side vector staging mapping (threads < 48): arr in {dstv, ed1, ed2}
    const int smarr = tid >> 4, smf4 = tid & 15;

    // B tile load mapping: 64 rows x 64 bf16 = 512 uint4, 2 per thread
    const int brow0 = tid >> 3,          bcol0 = tid & 7;
    const int brow1 = (tid + 256) >> 3,  bcol1 = tid & 7;

    // mma warp mapping: warp -> (row slab = wid&3, o-half = wid>>2)
    const int slab  = wid & 3;
    const int ohalf = wid >> 2;
    const int mbase = slab * 32;
    const int a_row = ((lane >> 3) & 1) * 8 + (lane & 7);
    const int a_k   = (lane >> 4) * 8;
    const uint32_t aAddr = smb + P_OFF + (mbase + a_row) * 144 + a_k * 2;
    const int b_n = ((lane >> 4) & 1) * 8 + (lane & 7);
    const int b_k = ((lane >> 3) & 1) * 8;
    const uint32_t bAddr = smb + B_OFF + (ohalf * 32 + b_n) * 144 + b_k * 2;

    float acc[2][4][4];     // [row 16-slab][o-frag][c]
    #pragma unroll
    for (int a = 0; a < 2; a++)
        #pragma unroll
        for (int b = 0; b < 4; b++)
            #pragma unroll
            for (int cc = 0; cc < 4; cc++) acc[a][b][cc] = 0.0f;
    float den = 0.0f;

    for (int c = 0; c < NN / 64; c++) {
        const int mt = c << 6;
        // ---- prefetch gmem to registers ----
        float4 a4[8];
        #pragma unroll
        for (int r = 0; r < 8; r++)
            a4[r] = *(const float4*)(adjrow + mt + mhalf + r * 4);
        uint4 bq0 = *(const uint4*)(g_hpT + ((size_t)kh * 64 + brow0) * NN + mt + bcol0 * 8);
        uint4 bq1 = *(const uint4*)(g_hpT + ((size_t)kh * 64 + brow1) * NN + mt + bcol1 * 8);
        float4 mv;
        if (tid < 48) {
            const float* src = (smarr == 0 ? g_dstv : (smarr == 1 ? g_ed1 : g_ed2))
                               + kh * NN + mt + smf4 * 4;
            mv = *(const float4*)src;
        }
        __syncthreads();   // prior chunk's ldmatrix reads complete
        // ---- stage smem ----
        if (tid < 48)
            *(float4*)(sm + V_OFF + smarr * 256 + smf4 * 16) = mv;
        *(uint4*)(sm + B_OFF + brow0 * 144 + bcol0 * 16) = bq0;
        *(uint4*)(sm + B_OFF + brow1 * 144 + bcol1 * 16) = bq1;
        __syncthreads();   // m-vectors visible to all
        // ---- build P tile (bf16) + accumulate denominator ----
        {
            const float* sdv = (const float*)(sm + V_OFF);
            const float* sq1 = (const float*)(sm + V_OFF + 256);
            const float* sq2 = (const float*)(sm + V_OFF + 512);
            float d0 = 0.0f;
            #pragma unroll
            for (int r = 0; r < 8; r++) {
                const int ml = mhalf + r * 4;
                const float4 dv = *(const float4*)(sdv + ml);
                const float4 q1 = *(const float4*)(sq1 + ml);
                const float4 q2 = *(const float4*)(sq2 + ml);
                const float p0 = a4[r].x * ((dv.x >= thr) ? E1 * q1.x : E2 * q2.x);
                const float p1 = a4[r].y * ((dv.y >= thr) ? E1 * q1.y : E2 * q2.y);
                const float p2 = a4[r].z * ((dv.z >= thr) ? E1 * q1.z : E2 * q2.z);
                const float p3 = a4[r].w * ((dv.w >= thr) ? E1 * q1.w : E2 * q2.w);
                d0 += (p0 + p1) + (p2 + p3);
                __nv_bfloat162 lo = __floats2bfloat162_rn(p0, p1);
                __nv_bfloat162 hi = __floats2bfloat162_rn(p2, p3);
                uint2 v;
                v.x = *(uint32_t*)&lo;
                v.y = *(uint32_t*)&hi;
                *(uint2*)(sm + P_OFF + i * 144 + ml * 2) = v;
            }
            den += d0;
        }
        __syncthreads();   // P + B tiles visible
        // ---- tensor cores: 32 x m16n8k16 per warp ----
        #pragma unroll
        for (int ks = 0; ks < 4; ks++) {
            uint32_t af0[4], af1[4];
            ldsm_x4(af0, aAddr + ks * 32);
            ldsm_x4(af1, aAddr + 16 * 144 + ks * 32);
            #pragma unroll
            for (int nt = 0; nt < 2; nt++) {
                uint32_t bf[4];
                ldsm_x4(bf, bAddr + nt * (16 * 144) + ks * 32);
                mma16816(acc[0][2 * nt],     af0, bf);
                mma16816(acc[0][2 * nt + 1], af0, bf + 2);
                mma16816(acc[1][2 * nt],     af1, bf);
                mma16816(acc[1][2 * nt + 1], af1, bf + 2);
            }
        }
    }

    // ---- denominator reduce: pairs (tid, tid^1) share row i ----
    float ds = den + __shfl_xor_sync(0xFFFFFFFFu, den, 1);
    if ((tid & 1) == 0)
        ((float*)(sm + D_OFF))[i] = ds;
    __syncthreads();

    // ---- epilogue: scale by 1/den, store ----
    const float* sden = (const float*)(sm + D_OFF);
    #pragma unroll
    for (int mt2 = 0; mt2 < 2; mt2++) {
        const int row0 = mbase + mt2 * 16 + (lane >> 2);
        const float inv0 = 1.0f / sden[row0];
        const float inv1 = 1.0f / sden[row0 + 8];
        float* op0 = g_att + ((size_t)kh * NN + n0 + row0) * OO;
        float* op1 = op0 + 8 * OO;
        #pragma unroll
        for (int j = 0; j < 4; j++) {
            const int col = ohalf * 32 + j * 8 + (lane & 3) * 2;
            float2 v0 = make_float2(acc[mt2][j][0] * inv0, acc[mt2][j][1] * inv0);
            float2 v1 = make_float2(acc[mt2][j][2] * inv1, acc[mt2][j][3] * inv1);
            *(float2*)(op0 + col) = v0;
            *(float2*)(op1 + col) = v1;
        }
    }
}

// ---------------------------------------------------------------------------
// Kernel 4: head-mean -> concat -> fc (C=2) -> log_softmax.
// ---------------------------------------------------------------------------
__global__ void k_final(const float* __restrict__ fc_w, const float* __restrict__ fc_b,
                        float* __restrict__ out) {
    const int wg = blockIdx.x * 8 + (threadIdx.x >> 5);
    if (wg >= NUSER) return;
    const int lane = threadIdx.x & 31;
    const int n = wg;

    float l0 = 0.0f, l1 = 0.0f;
    #pragma unroll
    for (int u = 0; u < 4; u++) {
        const int d = lane + u * 32;
        const int k = d >> 6, o = d & 63;
        float e = 0.0f;
        #pragma unroll
        for (int h = 0; h < HH; h++)
            e += g_att[(((size_t)(k * HH + h) * NN) + n) * OO + o];
        e *= 0.25f;
        l0 += e * fc_w[d];
        l1 += e * fc_w[128 + d];
    }
    #pragma unroll
    for (int off = 16; off; off >>= 1) {
        l0 += __shfl_xor_sync(0xFFFFFFFFu, l0, off);
        l1 += __shfl_xor_sync(0xFFFFFFFFu, l1, off);
    }
    if (lane == 0) {
        l0 += fc_b[0];
        l1 += fc_b[1];
        const float mx  = fmaxf(l0, l1);
        const float lse = mx + logf(expf(l0 - mx) + expf(l1 - mx));
        out[n * 2 + 0] = l0 - lse;
        out[n * 2 + 1] = l1 - lse;
    }
}

// ---------------------------------------------------------------------------
extern "C" void kernel_launch(void* const* d_in, const int* in_sizes, int n_in,
                              void* d_out, int out_size) {
    (void)in_sizes; (void)n_in; (void)out_size;
    const float* h     = (const float*)d_in[0];
    const float* hadj  = (const float*)d_in[1];
    const float* w     = (const float*)d_in[2];
    const float* a_src = (const float*)d_in[3];
    const float* a_dst = (const float*)d_in[4];
    const float* fc_w  = (const float*)d_in[5];
    const float* fc_b  = (const float*)d_in[6];
    float* out = (float*)d_out;

    static int smem_set = 0;
    if (!smem_set) {
        cudaFuncSetAttribute(k_main4, cudaFuncAttributeMaxDynamicSharedMemorySize, SMEM_DYN);
        smem_set = 1;
    }

    k_hproj <<<dim3(NN / 64, KHT), 256>>>(h, w);
    k_attvec<<<(KHT * NN) / 8, 256>>>(a_src, a_dst);
    k_main4 <<<dim3(NN / 128, KK, HH), 256, SMEM_DYN>>>(hadj);
    k_final <<<NUSER / 8, 256>>>(fc_w, fc_b, out);
}

// round 8
// speedup vs baseline: 1.9281x; 1.9281x over previous
#include <cuda_runtime.h>
#include <cuda_bf16.h>
#include <math.h>
#include <stdint.h>

// Problem constants
#define NN    4096
#define DD    64
#define HH    4
#define OO    64
#define KK    2
#define KHT   8        // K*H
#define NUSER 4000
#define CC    2

// Device scratch (allocation-free rule: static __device__ arrays)
__device__ float         g_hp [KHT * NN * OO];   // h_prime[kh][n][o]  fp32 (8 MB)
__device__ __nv_bfloat16 g_hpT[KHT * OO * NN];   // h_prime transposed [kh][o][m] bf16 (4 MB)
__device__ float         g_att[KHT * NN * OO];   // attention output per (k,h)  (8 MB)
__device__ float g_thr [KHT * NN];       // -src[n]
__device__ float g_es1 [KHT * NN];       // exp(src)
__device__ float g_es2 [KHT * NN];       // exp(0.2*src)
__device__ float g_dstv[KHT * NN];       // dst[m]
__device__ float g_ed1 [KHT * NN];       // exp(dst)
__device__ float g_ed2 [KHT * NN];       // exp(0.2*dst)

// ---------------------------------------------------------------------------
// Arch-agnostic tensor-core helpers (generic PTX, works on compute_103)
// ---------------------------------------------------------------------------
__device__ __forceinline__ uint32_t smem_u32(const void* p) {
    uint32_t a;
    asm("{ .reg .u64 t; cvta.to.shared.u64 t, %1; cvt.u32.u64 %0, t; }" : "=r"(a) : "l"(p));
    return a;
}
__device__ __forceinline__ void ldsm_x4(uint32_t* r, uint32_t addr) {
    asm volatile("ldmatrix.sync.aligned.m8n8.x4.shared.b16 {%0,%1,%2,%3}, [%4];"
        : "=r"(r[0]), "=r"(r[1]), "=r"(r[2]), "=r"(r[3]) : "r"(addr));
}
__device__ __forceinline__ void mma16816(float* c, const uint32_t* a, const uint32_t* b) {
    asm volatile("mma.sync.aligned.m16n8k16.row.col.f32.bf16.bf16.f32 "
        "{%0,%1,%2,%3}, {%4,%5,%6,%7}, {%8,%9}, {%0,%1,%2,%3};"
        : "+f"(c[0]), "+f"(c[1]), "+f"(c[2]), "+f"(c[3])
        : "r"(a[0]), "r"(a[1]), "r"(a[2]), "r"(a[3]), "r"(b[0]), "r"(b[1]));
}

// ---------------------------------------------------------------------------
// Kernel 1: h_prime = h @ w, plus bf16 transposed copy for the MMA B operand.
// grid (N/64, KH), 256 threads.
// ---------------------------------------------------------------------------
__global__ void k_hproj(const float* __restrict__ h, const float* __restrict__ w) {
    const int kh = blockIdx.y;
    const int n0 = blockIdx.x * 64;
    __shared__ float shT[64][68];     // [d][i]  (transposed h tile)
    __shared__ float buf[64 * 68];    // first 4096 floats: w tile; reused as [o][n] (stride 68)
    const int tid = threadIdx.x;

    const float4* wkh = (const float4*)(w + (size_t)kh * 64 * 64);
    #pragma unroll
    for (int it = 0; it < 4; it++) ((float4*)buf)[tid + it * 256] = wkh[tid + it * 256];

    {
        const int d = tid & 63, ig0 = tid >> 6;
        #pragma unroll
        for (int it = 0; it < 4; it++) {
            const int ig = ig0 + it * 4;
            float4 v;
            v.x = h[(size_t)(n0 + ig * 4 + 0) * DD + d];
            v.y = h[(size_t)(n0 + ig * 4 + 1) * DD + d];
            v.z = h[(size_t)(n0 + ig * 4 + 2) * DD + d];
            v.w = h[(size_t)(n0 + ig * 4 + 3) * DD + d];
            *(float4*)&shT[d][ig * 4] = v;
        }
    }
    __syncthreads();

    const int ty = tid >> 4, tx = tid & 15;
    float acc[4][4] = {};
    #pragma unroll 8
    for (int j = 0; j < 64; j++) {
        const float4 pv = *(const float4*)&shT[j][ty * 4];
        const float4 hv = *(const float4*)&buf[j * 64 + tx * 4];
        acc[0][0] += pv.x * hv.x; acc[0][1] += pv.x * hv.y; acc[0][2] += pv.x * hv.z; acc[0][3] += pv.x * hv.w;
        acc[1][0] += pv.y * hv.x; acc[1][1] += pv.y * hv.y; acc[1][2] += pv.y * hv.z; acc[1][3] += pv.y * hv.w;
        acc[2][0] += pv.z * hv.x; acc[2][1] += pv.z * hv.y; acc[2][2] += pv.z * hv.z; acc[2][3] += pv.z * hv.w;
        acc[3][0] += pv.w * hv.x; acc[3][1] += pv.w * hv.y; acc[3][2] += pv.w * hv.z; acc[3][3] += pv.w * hv.w;
    }
    // fp32 h_prime (for k_attvec)
    float* hp = g_hp + (size_t)kh * NN * OO;
    #pragma unroll
    for (int r = 0; r < 4; r++) {
        float4 v = make_float4(acc[r][0], acc[r][1], acc[r][2], acc[r][3]);
        *(float4*)&hp[(size_t)(n0 + ty * 4 + r) * OO + tx * 4] = v;
    }
    __syncthreads();            // done reading buf as w-tile
    // transpose into buf as [o][n_local], stride 68 to avoid conflicts
    #pragma unroll
    for (int r = 0; r < 4; r++)
        #pragma unroll
        for (int c = 0; c < 4; c++)
            buf[(tx * 4 + c) * 68 + ty * 4 + r] = acc[r][c];
    __syncthreads();
    // write bf16 transposed rows: thread -> row o = tid>>2, 16 n values
    {
        const int o = tid >> 2, nc = (tid & 3) * 16;
        __nv_bfloat162 tmp[8];
        #pragma unroll
        for (int j = 0; j < 8; j++)
            tmp[j] = __floats2bfloat162_rn(buf[o * 68 + nc + 2 * j], buf[o * 68 + nc + 2 * j + 1]);
        __nv_bfloat16* dst = g_hpT + ((size_t)kh * 64 + o) * NN + n0 + nc;
        *(uint4*)dst       = ((uint4*)tmp)[0];
        *(uint4*)(dst + 8) = ((uint4*)tmp)[1];
    }
}

// ---------------------------------------------------------------------------
// Kernel 2: src/dst attention scalars + factorized exponentials.
// ---------------------------------------------------------------------------
__global__ void k_attvec(const float* __restrict__ a_src, const float* __restrict__ a_dst) {
    const int wg   = blockIdx.x * 8 + (threadIdx.x >> 5);
    const int lane = threadIdx.x & 31;
    const int kh = wg >> 12;
    const int n  = wg & (NN - 1);
    const float* hp = g_hp + ((size_t)kh * NN + n) * OO;
    const float t1 = tanhf(hp[lane]);
    const float t2 = tanhf(hp[lane + 32]);
    float as = t1 * a_src[kh * 64 + lane] + t2 * a_src[kh * 64 + lane + 32];
    float ad = t1 * a_dst[kh * 64 + lane] + t2 * a_dst[kh * 64 + lane + 32];
    #pragma unroll
    for (int off = 16; off; off >>= 1) {
        as += __shfl_xor_sync(0xFFFFFFFFu, as, off);
        ad += __shfl_xor_sync(0xFFFFFFFFu, ad, off);
    }
    if (lane == 0) {
        const int idx = kh * NN + n;
        g_thr [idx] = -as;
        g_es1 [idx] = expf(as);
        g_es2 [idx] = expf(0.2f * as);
        g_dstv[idx] = ad;
        g_ed1 [idx] = expf(ad);
        g_ed2 [idx] = expf(0.2f * ad);
    }
}

// ---------------------------------------------------------------------------
// Kernel 3 (dominant, mma.sync bf16): ONE head per CTA, COALESCED adj loads.
//   D[128,64] += P[128,64]_bf16 @ HpT[64(o),64(m)]_bf16^T   (chunks over m)
//   P[n,m] = adj[k][n][m] * (dst[m] >= -src[n] ? es1[n]*ed1[m] : es2[n]*ed2[m])
// grid (N/128=32, K=2, H=4), 256 threads (8 warps), dynamic smem ~30KB.
// P-build ownership: thread -> fixed 4 cols (cbase=(tid&15)*4), 8 rows
// (row = (tid>>4) + j*16). Adj LDG.128 touches 4 lines/warp (was 32).
//
// smem (bytes from base):
//   P tile : [128 rows x 72 bf16 (144B stride)] = 18432
//   B tile : [ 64 rows x 72 bf16 (144B stride)] =  9216
//   row consts: 3 x 128 floats                  =  1536
//   den    : 128 floats                         =   512
// ---------------------------------------------------------------------------
#define P_OFF   0
#define B_OFF   18432
#define RC_OFF  27648
#define D_OFF   29184
#define SMEM_DYN 29696

__global__ void __launch_bounds__(256, 2) k_main5(const float* __restrict__ adj) {
    extern __shared__ char sm[];
    const uint32_t smb = smem_u32(sm);
    const int tid  = threadIdx.x;
    const int wid  = tid >> 5;
    const int lane = tid & 31;
    const int k    = blockIdx.y;
    const int hh   = blockIdx.z;
    const int n0   = blockIdx.x * 128;
    const int kh   = k * HH + hh;

    // stage row-side constants into smem (visible after first loop sync)
    if (tid < 128) {
        const int ridx = kh * NN + n0 + tid;
        ((float*)(sm + RC_OFF))[tid]       = g_thr[ridx];
        ((float*)(sm + RC_OFF))[128 + tid] = g_es1[ridx];
        ((float*)(sm + RC_OFF))[256 + tid] = g_es2[ridx];
    }

    // P-build mapping: fixed cols, walk rows
    const int g     = tid >> 4;          // 0..15
    const int cbase = (tid & 15) * 4;    // 0..60
    const float* adjbase = adj + (size_t)k * NN * NN + (size_t)n0 * NN;
    const float* mdv = g_dstv + kh * NN;
    const float* me1 = g_ed1  + kh * NN;
    const float* me2 = g_ed2  + kh * NN;

    // B tile load mapping: 64 rows x 64 bf16 = 512 uint4, 2 per thread
    const int brow0 = tid >> 3,          bcol0 = tid & 7;
    const int brow1 = (tid + 256) >> 3,  bcol1 = tid & 7;

    // mma warp mapping: warp -> (row slab = wid&3, o-half = wid>>2)
    const int slab  = wid & 3;
    const int ohalf = wid >> 2;
    const int mbase = slab * 32;
    const int a_row = ((lane >> 3) & 1) * 8 + (lane & 7);
    const int a_k   = (lane >> 4) * 8;
    const uint32_t aAddr = smb + P_OFF + (mbase + a_row) * 144 + a_k * 2;
    const int b_n = ((lane >> 4) & 1) * 8 + (lane & 7);
    const int b_k = ((lane >> 3) & 1) * 8;
    const uint32_t bAddr = smb + B_OFF + (ohalf * 32 + b_n) * 144 + b_k * 2;

    float acc[2][4][4];     // [row 16-slab][o-frag][c]
    #pragma unroll
    for (int a = 0; a < 2; a++)
        #pragma unroll
        for (int b = 0; b < 4; b++)
            #pragma unroll
            for (int cc = 0; cc < 4; cc++) acc[a][b][cc] = 0.0f;
    float den[8];
    #pragma unroll
    for (int j = 0; j < 8; j++) den[j] = 0.0f;

    const float* sthr = (const float*)(sm + RC_OFF);

    for (int c = 0; c < NN / 64; c++) {
        const int mt = c << 6;
        // ---- prefetch gmem to registers (coalesced) ----
        float4 a4[8];
        #pragma unroll
        for (int j = 0; j < 8; j++)
            a4[j] = *(const float4*)(adjbase + (size_t)(g + j * 16) * NN + mt + cbase);
        const uint4 bq0 = *(const uint4*)(g_hpT + ((size_t)kh * 64 + brow0) * NN + mt + bcol0 * 8);
        const uint4 bq1 = *(const uint4*)(g_hpT + ((size_t)kh * 64 + brow1) * NN + mt + bcol1 * 8);
        const float4 dv4 = *(const float4*)(mdv + mt + cbase);
        const float4 q14 = *(const float4*)(me1 + mt + cbase);
        const float4 q24 = *(const float4*)(me2 + mt + cbase);

        __syncthreads();   // prior chunk's ldsm reads complete (also orders RC stage on c==0)

        // ---- stage B ----
        *(uint4*)(sm + B_OFF + brow0 * 144 + bcol0 * 16) = bq0;
        *(uint4*)(sm + B_OFF + brow1 * 144 + bcol1 * 16) = bq1;

        // ---- build P tile (bf16): 8 rows x 4 cols per thread ----
        #pragma unroll
        for (int j = 0; j < 8; j++) {
            const int row = g + j * 16;
            const float thr = sthr[row];
            const float e1  = sthr[128 + row];
            const float e2  = sthr[256 + row];
            const float p0 = a4[j].x * ((dv4.x >= thr) ? e1 * q14.x : e2 * q24.x);
            const float p1 = a4[j].y * ((dv4.y >= thr) ? e1 * q14.y : e2 * q24.y);
            const float p2 = a4[j].z * ((dv4.z >= thr) ? e1 * q14.z : e2 * q24.z);
            const float p3 = a4[j].w * ((dv4.w >= thr) ? e1 * q14.w : e2 * q24.w);
            den[j] += (p0 + p1) + (p2 + p3);
            __nv_bfloat162 lo = __floats2bfloat162_rn(p0, p1);
            __nv_bfloat162 hi = __floats2bfloat162_rn(p2, p3);
            uint2 v;
            v.x = *(uint32_t*)&lo;
            v.y = *(uint32_t*)&hi;
            *(uint2*)(sm + P_OFF + row * 144 + cbase * 2) = v;
        }
        __syncthreads();   // P + B tiles visible

        // ---- tensor cores: 32 x m16n8k16 per warp ----
        #pragma unroll
        for (int ks = 0; ks < 4; ks++) {
            uint32_t af0[4], af1[4];
            ldsm_x4(af0, aAddr + ks * 32);
            ldsm_x4(af1, aAddr + 16 * 144 + ks * 32);
            #pragma unroll
            for (int nt = 0; nt < 2; nt++) {
                uint32_t bf[4];
                ldsm_x4(bf, bAddr + nt * (16 * 144) + ks * 32);
                mma16816(acc[0][2 * nt],     af0, bf);
                mma16816(acc[0][2 * nt + 1], af0, bf + 2);
                mma16816(acc[1][2 * nt],     af1, bf);
                mma16816(acc[1][2 * nt + 1], af1, bf + 2);
            }
        }
    }

    // ---- denominator reduce: 16 col-owner lanes per row ----
    #pragma unroll
    for (int j = 0; j < 8; j++) {
        float v = den[j];
        v += __shfl_xor_sync(0xFFFFFFFFu, v, 8);
        v += __shfl_xor_sync(0xFFFFFFFFu, v, 4);
        v += __shfl_xor_sync(0xFFFFFFFFu, v, 2);
        v += __shfl_xor_sync(0xFFFFFFFFu, v, 1);
        if ((tid & 15) == 0)
            ((float*)(sm + D_OFF))[g + j * 16] = v;
    }
    __syncthreads();

    // ---- epilogue: scale by 1/den, store ----
    const float* sden = (const float*)(sm + D_OFF);
    #pragma unroll
    for (int mt2 = 0; mt2 < 2; mt2++) {
        const int row0 = mbase + mt2 * 16 + (lane >> 2);
        const float inv0 = 1.0f / sden[row0];
        const float inv1 = 1.0f / sden[row0 + 8];
        float* op0 = g_att + ((size_t)kh * NN + n0 + row0) * OO;
        float* op1 = op0 + 8 * OO;
        #pragma unroll
        for (int j = 0; j < 4; j++) {
            const int col = ohalf * 32 + j * 8 + (lane & 3) * 2;
            float2 v0 = make_float2(acc[mt2][j][0] * inv0, acc[mt2][j][1] * inv0);
            float2 v1 = make_float2(acc[mt2][j][2] * inv1, acc[mt2][j][3] * inv1);
            *(float2*)(op0 + col) = v0;
            *(float2*)(op1 + col) = v1;
        }
    }
}

// ---------------------------------------------------------------------------
// Kernel 4: head-mean -> concat -> fc (C=2) -> log_softmax.
// ---------------------------------------------------------------------------
__global__ void k_final(const float* __restrict__ fc_w, const float* __restrict__ fc_b,
                        float* __restrict__ out) {
    const int wg = blockIdx.x * 8 + (threadIdx.x >> 5);
    if (wg >= NUSER) return;
    const int lane = threadIdx.x & 31;
    const int n = wg;

    float l0 = 0.0f, l1 = 0.0f;
    #pragma unroll
    for (int u = 0; u < 4; u++) {
        const int d = lane + u * 32;
        const int k = d >> 6, o = d & 63;
        float e = 0.0f;
        #pragma unroll
        for (int h = 0; h < HH; h++)
            e += g_att[(((size_t)(k * HH + h) * NN) + n) * OO + o];
        e *= 0.25f;
        l0 += e * fc_w[d];
        l1 += e * fc_w[128 + d];
    }
    #pragma unroll
    for (int off = 16; off; off >>= 1) {
        l0 += __shfl_xor_sync(0xFFFFFFFFu, l0, off);
        l1 += __shfl_xor_sync(0xFFFFFFFFu, l1, off);
    }
    if (lane == 0) {
        l0 += fc_b[0];
        l1 += fc_b[1];
        const float mx  = fmaxf(l0, l1);
        const float lse = mx + logf(expf(l0 - mx) + expf(l1 - mx));
        out[n * 2 + 0] = l0 - lse;
        out[n * 2 + 1] = l1 - lse;
    }
}

// ---------------------------------------------------------------------------
extern "C" void kernel_launch(void* const* d_in, const int* in_sizes, int n_in,
                              void* d_out, int out_size) {
    (void)in_sizes; (void)n_in; (void)out_size;
    const float* h     = (const float*)d_in[0];
    const float* hadj  = (const float*)d_in[1];
    const float* w     = (const float*)d_in[2];
    const float* a_src = (const float*)d_in[3];
    const float* a_dst = (const float*)d_in[4];
    const float* fc_w  = (const float*)d_in[5];
    const float* fc_b  = (const float*)d_in[6];
    float* out = (float*)d_out;

    static int smem_set = 0;
    if (!smem_set) {
        cudaFuncSetAttribute(k_main5, cudaFuncAttributeMaxDynamicSharedMemorySize, SMEM_DYN);
        smem_set = 1;
    }

    k_hproj <<<dim3(NN / 64, KHT), 256>>>(h, w);
    k_attvec<<<(KHT * NN) / 8, 256>>>(a_src, a_dst);
    k_main5 <<<dim3(NN / 128, KK, HH), 256, SMEM_DYN>>>(hadj);
    k_final <<<NUSER / 8, 256>>>(fc_w, fc_b, out);
}